// round 11
// baseline (speedup 1.0000x reference)
#include <cuda_runtime.h>
#include <cuda_bf16.h>
#include <cstdint>

#define N_ATOM 50000
#define M_NBR  12
#define NM_TOT 600000
#define F_DIM  128
#define FAN_IN 320
#define EPS    1e-5f

// ---------------- scratch ----------------------------------------------------
__device__ __align__(16) float g_SA[(size_t)N_ATOM * 512];      // [n][0:256)=S, [256:512)=A
__device__ __align__(16) float g_nbr[(size_t)N_ATOM * F_DIM];
__device__ float g_stats1[512];
__device__ float g_stats2[256];
__device__ float g_bn1[512];
__device__ float g_bn2[256];
__device__ int   g_idx32[NM_TOT];
__device__ int   g_is64;
__device__ __align__(16) __nv_bfloat16 g_Wh[256 * 64];     // W_edge hi, K-major
__device__ __align__(16) __nv_bfloat16 g_Wl[256 * 64];     // W_edge lo
__device__ __align__(16) __nv_bfloat16 g_WSh[512 * 128];   // [S|A] weights hi
__device__ __align__(16) __nv_bfloat16 g_WSl[512 * 128];   // [S|A] weights lo

__device__ __forceinline__ float softplusf(float x) {
    return fmaxf(x, 0.f) + __logf(1.f + __expf(-fabsf(x)));
}
__device__ __forceinline__ float sigmoidf(float x) {
    return 1.f / (1.f + __expf(-x));
}
__device__ __forceinline__ uint32_t smem_u32(const void* p) {
    uint32_t a;
    asm("{ .reg .u64 t; cvta.to.shared.u64 t, %1; cvt.u32.u64 %0, t; }"
        : "=r"(a) : "l"(p));
    return a;
}
__device__ __forceinline__ uint32_t pkbf(__nv_bfloat16 a, __nv_bfloat16 b) {
    __nv_bfloat162 t = __halves2bfloat162(a, b);
    return *(uint32_t*)&t;
}
__device__ __forceinline__ void ldsm_x4(uint32_t* r, uint32_t addr) {
    asm volatile("ldmatrix.sync.aligned.m8n8.x4.shared.b16 {%0,%1,%2,%3}, [%4];"
        : "=r"(r[0]), "=r"(r[1]), "=r"(r[2]), "=r"(r[3]) : "r"(addr));
}
__device__ __forceinline__ void mma_bf16(float* c, const uint32_t* a,
                                         uint32_t b0, uint32_t b1) {
    asm volatile("mma.sync.aligned.m16n8k16.row.col.f32.bf16.bf16.f32 "
        "{%0,%1,%2,%3}, {%4,%5,%6,%7}, {%8,%9}, {%0,%1,%2,%3};"
        : "+f"(c[0]), "+f"(c[1]), "+f"(c[2]), "+f"(c[3])
        : "r"(a[0]), "r"(a[1]), "r"(a[2]), "r"(a[3]), "r"(b0), "r"(b1));
}

// pass1 smem layout (73728 B) — identical to R9 gate2
#define GB_BIAS 0
#define GB_STAT 512
#define GB_S    1536
#define GB_A    8192
#define GB_W    40960
#define GB_TOTAL 73728

// sa kernel smem layout (98304 B)
#define SB_A 0
#define SB_W 65536
#define SB_TOTAL 98304

// pass2 smem layout (86016 B). P overlays A+W after mainloop.
#define P2_BIAS 0          // 256 floats
#define P2_BN   1024       // 512 floats (sc[256], sh[256])
#define P2_MSK  3072       // 64 floats
#define P2_A    4096       // 64 rows x 16 chunks x 16B = 16384
#define P2_W    20480      // 256 rows x 16 chunks x 16B = 65536
#define P2_P    4096       // overlay: 64 rows x 258 floats = 66048
#define P2_TOTAL 86016

// ---------------- k_detect ---------------------------------------------------
__global__ void k_detect(const int* __restrict__ raw) {
    __shared__ int any;
    if (threadIdx.x == 0) any = 0;
    __syncthreads();
    if (raw[threadIdx.x * 2 + 1] != 0) atomicOr(&any, 1);
    __syncthreads();
    if (threadIdx.x == 0) g_is64 = any ? 0 : 1;
}

// ---------------- k_convert: idx normalize + zero accumulators ---------------
__global__ void k_convert(const int* __restrict__ raw) {
    int i = blockIdx.x * blockDim.x + threadIdx.x;
    int nth = gridDim.x * blockDim.x;
    if (i < NM_TOT) g_idx32[i] = g_is64 ? raw[2 * i] : raw[i];
    if (i < 512) g_stats1[i] = 0.f;
    if (i < 256) g_stats2[i] = 0.f;
    for (int k = i; k < N_ATOM * 128; k += nth) g_nbr[k] = 0.f;
}

// ---------------- k_wconv: split W_edge into bf16 hi/lo ----------------------
__global__ void k_wconv(const float* __restrict__ W) {
    int i = blockIdx.x * blockDim.x + threadIdx.x;
    if (i < 256 * 64) {
        int f = i >> 6, k = i & 63;
        float w = W[f * FAN_IN + 256 + k];
        __nv_bfloat16 h = __float2bfloat16(w);
        g_Wh[i] = h;
        g_Wl[i] = __float2bfloat16(w - __bfloat162float(h));
    }
}

// ---------------- k_wconv2: split [W_self; W_nbr] into bf16 hi/lo ------------
__global__ void k_wconv2(const float* __restrict__ W) {
    int i = blockIdx.x * blockDim.x + threadIdx.x;   // 512*128
    int f = i >> 7, k = i & 127;
    float w = (f < 256) ? W[f * FAN_IN + k] : W[(f - 256) * FAN_IN + 128 + k];
    __nv_bfloat16 h = __float2bfloat16(w);
    g_WSh[i] = h;
    g_WSl[i] = __float2bfloat16(w - __bfloat162float(h));
}

// ---------------- k1: [S|A] via HMMA bf16 hi/lo (R9-proven) ------------------
__global__ __launch_bounds__(256) void k_sa_hmma(const float* __restrict__ atom) {
    extern __shared__ char smem[];
    const uint32_t sb = smem_u32(smem);
    const int tid = threadIdx.x;
    const int wid = tid >> 5, lane = tid & 31;
    const int fbase = blockIdx.x * 64;
    const int row0  = blockIdx.y * 128;
    const int rw0 = wid * 16;

    for (int t = tid; t < 2048; t += 256) {
        int r = t >> 4, c = t & 15;
        int gr = row0 + r; if (gr >= N_ATOM) gr = N_ATOM - 1;
        float4 v0 = *(const float4*)(atom + (size_t)gr * 128 + c * 8);
        float4 v1 = *(const float4*)(atom + (size_t)gr * 128 + c * 8 + 4);
        float xs[8] = {v0.x, v0.y, v0.z, v0.w, v1.x, v1.y, v1.z, v1.w};
        __nv_bfloat16 h[8]; float l[8];
#pragma unroll
        for (int q = 0; q < 8; q++) {
            h[q] = __float2bfloat16(xs[q]);
            l[q] = xs[q] - __bfloat162float(h[q]);
        }
        uint4 hh = make_uint4(pkbf(h[0], h[1]), pkbf(h[2], h[3]),
                              pkbf(h[4], h[5]), pkbf(h[6], h[7]));
        uint4 ll = make_uint4(
            pkbf(__float2bfloat16(l[0]), __float2bfloat16(l[1])),
            pkbf(__float2bfloat16(l[2]), __float2bfloat16(l[3])),
            pkbf(__float2bfloat16(l[4]), __float2bfloat16(l[5])),
            pkbf(__float2bfloat16(l[6]), __float2bfloat16(l[7])));
        int base = r * 512;
        *(uint4*)(smem + SB_A + base + (((c)      ^ (r & 7)) << 4)) = hh;
        *(uint4*)(smem + SB_A + base + (((c + 16) ^ (r & 7)) << 4)) = ll;
    }
    for (int t = tid; t < 1024; t += 256) {
        int r = t >> 4, c = t & 15;
        int gf = fbase + r;
        uint4 hh = *(const uint4*)((const char*)g_WSh + (size_t)gf * 256 + c * 16);
        uint4 ll = *(const uint4*)((const char*)g_WSl + (size_t)gf * 256 + c * 16);
        int base = r * 512;
        *(uint4*)(smem + SB_W + base + (((c)      ^ (r & 7)) << 4)) = hh;
        *(uint4*)(smem + SB_W + base + (((c + 16) ^ (r & 7)) << 4)) = ll;
    }
    __syncthreads();

    float acc[8][4];
#pragma unroll
    for (int i = 0; i < 8; i++)
#pragma unroll
        for (int j = 0; j < 4; j++) acc[i][j] = 0.f;

    const int arow = rw0 + (lane & 15);
    const uint32_t a_base = sb + SB_A + arow * 512;
    const int asel = lane >> 4;
    const int brow_l = ((lane >> 4) << 3) + (lane & 7);
    const int bsel = (lane >> 3) & 1;

#pragma unroll
    for (int s = 0; s < 24; s++) {
        int grp = s >> 3, ss = s & 7;
        int ac = ((grp == 2) ? 16 : 0) + 2 * ss + asel;
        int bc = ((grp == 1) ? 16 : 0) + 2 * ss + bsel;
        uint32_t a[4];
        ldsm_x4(a, a_base + ((ac ^ (arow & 7)) << 4));
#pragma unroll
        for (int t = 0; t < 4; t++) {
            uint32_t b[4];
            int brow = t * 16 + brow_l;
            ldsm_x4(b, sb + SB_W + brow * 512 + ((bc ^ (brow & 7)) << 4));
            mma_bf16(acc[2 * t],     a, b[0], b[1]);
            mma_bf16(acc[2 * t + 1], a, b[2], b[3]);
        }
    }

    const int g = lane >> 2, tig = lane & 3;
#pragma unroll
    for (int nt = 0; nt < 8; nt++) {
        int col = fbase + nt * 8 + tig * 2;
#pragma unroll
        for (int rr = 0; rr < 2; rr++) {
            int gr = row0 + rw0 + g + rr * 8;
            if (gr < N_ATOM)
                *(float2*)(g_SA + (size_t)gr * 512 + col) =
                    make_float2(acc[nt][rr * 2], acc[nt][rr * 2 + 1]);
        }
    }
}

// ---------------- pass1: GEMM + gated stats ONLY (no store) ------------------
// grid (2, 4688), 256 threads. R9's k_gate2 minus the g_gated store.
__global__ __launch_bounds__(256) void k_pass1(const float* __restrict__ nbr,
                                               const float* __restrict__ bias) {
    extern __shared__ char smem[];
    const uint32_t sb = smem_u32(smem);
    const int tid = threadIdx.x;
    const int wid = tid >> 5, lane = tid & 31;
    const int fbase = blockIdx.x * 128;
    const int row0  = blockIdx.y * 128;
    const int rw0 = wid * 16;
    const int n0 = row0 / 12;

    if (tid < 128) *(float*)(smem + GB_BIAS + tid * 4) = bias[fbase + tid];
    if (tid < 256) *(float*)(smem + GB_STAT + tid * 4) = 0.f;

    for (int t = tid; t < 12 * 128; t += 256) {
        int nl = t >> 7, lc = t & 127;
        int gn = n0 + nl;
        float v = (gn < N_ATOM) ? g_SA[(size_t)gn * 512 + fbase + lc] : 0.f;
        *(float*)(smem + GB_S + t * 4) = v;
    }
    for (int t = tid; t < 1024; t += 256) {
        int r = t >> 3, c = t & 7;
        int gr = row0 + r; if (gr >= NM_TOT) gr = NM_TOT - 1;
        float4 v0 = *(const float4*)(nbr + (size_t)gr * 64 + c * 8);
        float4 v1 = *(const float4*)(nbr + (size_t)gr * 64 + c * 8 + 4);
        float xs[8] = {v0.x, v0.y, v0.z, v0.w, v1.x, v1.y, v1.z, v1.w};
        __nv_bfloat16 h[8]; float l[8];
#pragma unroll
        for (int q = 0; q < 8; q++) {
            h[q] = __float2bfloat16(xs[q]);
            l[q] = xs[q] - __bfloat162float(h[q]);
        }
        uint4 hh = make_uint4(pkbf(h[0], h[1]), pkbf(h[2], h[3]),
                              pkbf(h[4], h[5]), pkbf(h[6], h[7]));
        uint4 ll = make_uint4(
            pkbf(__float2bfloat16(l[0]), __float2bfloat16(l[1])),
            pkbf(__float2bfloat16(l[2]), __float2bfloat16(l[3])),
            pkbf(__float2bfloat16(l[4]), __float2bfloat16(l[5])),
            pkbf(__float2bfloat16(l[6]), __float2bfloat16(l[7])));
        int base = r * 256;
        *(uint4*)(smem + GB_A + base + (((c)     ^ (r & 7)) << 4)) = hh;
        *(uint4*)(smem + GB_A + base + (((c + 8) ^ (r & 7)) << 4)) = ll;
    }
    for (int t = tid; t < 1024; t += 256) {
        int r = t >> 3, c = t & 7;
        int gf = fbase + r;
        uint4 hh = *(const uint4*)((const char*)g_Wh + (size_t)gf * 128 + c * 16);
        uint4 ll = *(const uint4*)((const char*)g_Wl + (size_t)gf * 128 + c * 16);
        int base = r * 256;
        *(uint4*)(smem + GB_W + base + (((c)     ^ (r & 7)) << 4)) = hh;
        *(uint4*)(smem + GB_W + base + (((c + 8) ^ (r & 7)) << 4)) = ll;
    }
    __syncthreads();

    float acc[16][4];
#pragma unroll
    for (int i = 0; i < 16; i++)
#pragma unroll
        for (int j = 0; j < 4; j++) acc[i][j] = 0.f;

    const int KA[12] = {0,2,4,6, 0,2,4,6, 8,10,12,14};
    const int KW[12] = {0,2,4,6, 8,10,12,14, 0,2,4,6};
    const int arow = rw0 + (lane & 15);
    const uint32_t a_base = sb + GB_A + arow * 256;
    const int asel = lane >> 4;
    const int brow_l = ((lane >> 4) << 3) + (lane & 7);
    const int bsel = (lane >> 3) & 1;

#pragma unroll
    for (int s = 0; s < 12; s++) {
        uint32_t a[4];
        int ac = KA[s] + asel;
        ldsm_x4(a, a_base + ((ac ^ (arow & 7)) << 4));
        int bc = KW[s] + bsel;
#pragma unroll
        for (int t = 0; t < 8; t++) {
            uint32_t b[4];
            int brow = t * 16 + brow_l;
            ldsm_x4(b, sb + GB_W + brow * 256 + ((bc ^ (brow & 7)) << 4));
            mma_bf16(acc[2 * t],     a, b[0], b[1]);
            mma_bf16(acc[2 * t + 1], a, b[2], b[3]);
        }
    }

    // stats-only epilogue (R7/R9 pattern, no gated store)
    const int g = lane >> 2, tig = lane & 3;
    float* s_stat = (float*)(smem + GB_STAT);

    int nl[2], jj[2]; float mk[2]; bool val[2];
#pragma unroll
    for (int rr = 0; rr < 2; rr++) {
        int nm = row0 + rw0 + g + rr * 8;
        val[rr] = (nm < NM_TOT);
        int nmc = val[rr] ? nm : 0;
        nl[rr] = nmc / 12 - n0;
        jj[rr] = g_idx32[nmc];
        mk[rr] = (val[rr] && jj[rr] != 0) ? 1.f : 0.f;
    }

#pragma unroll
    for (int nt = 0; nt < 16; nt++) {
        int lcol = nt * 8 + tig * 2;
        int col = fbase + lcol;
        float2 b2 = *(const float2*)(smem + GB_BIAS + lcol * 4);
        float S0 = 0.f, S1 = 0.f, Q0 = 0.f, Q1 = 0.f;
#pragma unroll
        for (int rr = 0; rr < 2; rr++) {
            if (!val[rr]) continue;
            float2 s2 = *(const float2*)(smem + GB_S + (nl[rr] * 128 + lcol) * 4);
            float2 a2 = *(const float2*)(g_SA + (size_t)jj[rr] * 512 + 256 + col);
            float g0 = s2.x + b2.x + mk[rr] * (a2.x + acc[nt][rr * 2 + 0]);
            float g1 = s2.y + b2.y + mk[rr] * (a2.y + acc[nt][rr * 2 + 1]);
            S0 += g0; S1 += g1; Q0 += g0 * g0; Q1 += g1 * g1;
        }
#pragma unroll
        for (int s = 4; s <= 16; s <<= 1) {
            S0 += __shfl_xor_sync(0xffffffffu, S0, s);
            S1 += __shfl_xor_sync(0xffffffffu, S1, s);
            Q0 += __shfl_xor_sync(0xffffffffu, Q0, s);
            Q1 += __shfl_xor_sync(0xffffffffu, Q1, s);
        }
        if (lane < 4) {
            atomicAdd(&s_stat[lcol],           S0);
            atomicAdd(&s_stat[lcol + 1],       S1);
            atomicAdd(&s_stat[128 + lcol],     Q0);
            atomicAdd(&s_stat[128 + lcol + 1], Q1);
        }
    }
    __syncthreads();
    if (tid < 128)      atomicAdd(&g_stats1[fbase + tid],             s_stat[tid]);
    else                atomicAdd(&g_stats1[256 + fbase + tid - 128], s_stat[tid]);
}

// ---------------- k_fin1 ------------------------------------------------------
__global__ void k_fin1(const float* __restrict__ gamma1, const float* __restrict__ beta1) {
    int f = threadIdx.x;  // 256
    float inv = 1.f / (float)NM_TOT;
    float mean = g_stats1[f] * inv;
    float var  = g_stats1[256 + f] * inv - mean * mean;
    float sc = gamma1[f] * rsqrtf(var + EPS);
    g_bn1[f] = sc;
    g_bn1[256 + f] = beta1[f] - mean * sc;
}

// ---------------- pass2: GEMM 64x256 + BN1 + gate product -> g_nbr -----------
// grid 9375, 256 threads (8 warps: 4 row-groups x 2 col-groups of 128).
__global__ __launch_bounds__(256) void k_pass2(const float* __restrict__ nbr,
                                               const float* __restrict__ bias) {
    extern __shared__ char smem[];
    const uint32_t sb = smem_u32(smem);
    const int tid = threadIdx.x;
    const int wid = tid >> 5, lane = tid & 31;
    const int row0 = blockIdx.x * 64;        // 64 | 600000: no guards
    const int rw0 = (wid & 3) * 16;
    const int cg  = wid >> 2;                // 0: filter cols, 1: core cols

    if (tid < 256) *(float*)(smem + P2_BIAS + tid * 4) = bias[tid];
    for (int t = tid; t < 512; t += 256) *(float*)(smem + P2_BN + t * 4) = g_bn1[t];
    if (tid < 64)
        *(float*)(smem + P2_MSK + tid * 4) = (g_idx32[row0 + tid] != 0) ? 1.f : 0.f;

    // ---- fill A: 64 rows x 8 src chunks -> [Xh|Xl] ----
    for (int t = tid; t < 512; t += 256) {
        int r = t >> 3, c = t & 7;
        int gr = row0 + r;
        float4 v0 = *(const float4*)(nbr + (size_t)gr * 64 + c * 8);
        float4 v1 = *(const float4*)(nbr + (size_t)gr * 64 + c * 8 + 4);
        float xs[8] = {v0.x, v0.y, v0.z, v0.w, v1.x, v1.y, v1.z, v1.w};
        __nv_bfloat16 h[8]; float l[8];
#pragma unroll
        for (int q = 0; q < 8; q++) {
            h[q] = __float2bfloat16(xs[q]);
            l[q] = xs[q] - __bfloat162float(h[q]);
        }
        uint4 hh = make_uint4(pkbf(h[0], h[1]), pkbf(h[2], h[3]),
                              pkbf(h[4], h[5]), pkbf(h[6], h[7]));
        uint4 ll = make_uint4(
            pkbf(__float2bfloat16(l[0]), __float2bfloat16(l[1])),
            pkbf(__float2bfloat16(l[2]), __float2bfloat16(l[3])),
            pkbf(__float2bfloat16(l[4]), __float2bfloat16(l[5])),
            pkbf(__float2bfloat16(l[6]), __float2bfloat16(l[7])));
        int base = r * 256;
        *(uint4*)(smem + P2_A + base + (((c)     ^ (r & 7)) << 4)) = hh;
        *(uint4*)(smem + P2_A + base + (((c + 8) ^ (r & 7)) << 4)) = ll;
    }
    // ---- fill W: all 256 feature rows x 8 chunks -> [Wh|Wl] ----
    for (int t = tid; t < 2048; t += 256) {
        int r = t >> 3, c = t & 7;
        uint4 hh = *(const uint4*)((const char*)g_Wh + (size_t)r * 128 + c * 16);
        uint4 ll = *(const uint4*)((const char*)g_Wl + (size_t)r * 128 + c * 16);
        int base = r * 256;
        *(uint4*)(smem + P2_W + base + (((c)     ^ (r & 7)) << 4)) = hh;
        *(uint4*)(smem + P2_W + base + (((c + 8) ^ (r & 7)) << 4)) = ll;
    }
    __syncthreads();

    float acc[16][4];
#pragma unroll
    for (int i = 0; i < 16; i++)
#pragma unroll
        for (int j = 0; j < 4; j++) acc[i][j] = 0.f;

    const int KA[12] = {0,2,4,6, 0,2,4,6, 8,10,12,14};
    const int KW[12] = {0,2,4,6, 8,10,12,14, 0,2,4,6};
    const int arow = rw0 + (lane & 15);
    const uint32_t a_base = sb + P2_A + arow * 256;
    const int asel = lane >> 4;
    const int brow_l = ((lane >> 4) << 3) + (lane & 7);
    const int bsel = (lane >> 3) & 1;

#pragma unroll
    for (int s = 0; s < 12; s++) {
        uint32_t a[4];
        int ac = KA[s] + asel;
        ldsm_x4(a, a_base + ((ac ^ (arow & 7)) << 4));
        int bc = KW[s] + bsel;
#pragma unroll
        for (int t = 0; t < 8; t++) {
            uint32_t b[4];
            int brow = cg * 128 + t * 16 + brow_l;
            ldsm_x4(b, sb + P2_W + brow * 256 + ((bc ^ (brow & 7)) << 4));
            mma_bf16(acc[2 * t],     a, b[0], b[1]);
            mma_bf16(acc[2 * t + 1], a, b[2], b[3]);
        }
    }
    __syncthreads();   // A/W dead; P overlay safe

    // ---- stage activated values into P[64][258] ----
    float* P = (float*)(smem + P2_P);
    const int g = lane >> 2, tig = lane & 3;
    int jj[2]; float mk[2]; int nn[2];
#pragma unroll
    for (int rr = 0; rr < 2; rr++) {
        int nm = row0 + rw0 + g + rr * 8;
        nn[rr] = nm / 12;
        jj[rr] = g_idx32[nm];
        mk[rr] = (jj[rr] != 0) ? 1.f : 0.f;
    }
#pragma unroll
    for (int nt = 0; nt < 16; nt++) {
        int col = cg * 128 + nt * 8 + tig * 2;
        float2 b2  = *(const float2*)(smem + P2_BIAS + col * 4);
        float2 sc2 = *(const float2*)(smem + P2_BN + col * 4);
        float2 sh2 = *(const float2*)(smem + P2_BN + (256 + col) * 4);
#pragma unroll
        for (int rr = 0; rr < 2; rr++) {
            int row = rw0 + g + rr * 8;
            float2 s2 = *(const float2*)(g_SA + (size_t)nn[rr] * 512 + col);
            float2 a2 = *(const float2*)(g_SA + (size_t)jj[rr] * 512 + 256 + col);
            float g0 = s2.x + b2.x + mk[rr] * (a2.x + acc[nt][rr * 2 + 0]);
            float g1 = s2.y + b2.y + mk[rr] * (a2.y + acc[nt][rr * 2 + 1]);
            g0 = g0 * sc2.x + sh2.x;
            g1 = g1 * sc2.y + sh2.y;
            float p0, p1;
            if (cg == 0) { p0 = sigmoidf(g0);  p1 = sigmoidf(g1); }
            else         { p0 = softplusf(g0); p1 = softplusf(g1); }
            *(float2*)&P[row * 258 + col] = make_float2(p0, p1);
        }
    }
    __syncthreads();

    // ---- product + per-atom reduce -> g_nbr atomics ----
    {
        const float* mskp = (const float*)(smem + P2_MSK);
        int f = tid & 127;
        int half = tid >> 7;              // rows half*32 .. +31
        int rbeg = half * 32;
        float accv = 0.f;
        int cur_n = (row0 + rbeg) / 12;
#pragma unroll 8
        for (int row = rbeg; row < rbeg + 32; row++) {
            int n = (row0 + row) / 12;
            if (n != cur_n) {
                atomicAdd(&g_nbr[(size_t)cur_n * 128 + f], accv);
                accv = 0.f; cur_n = n;
            }
            accv += mskp[row] * P[row * 258 + f] * P[row * 258 + 128 + f];
        }
        atomicAdd(&g_nbr[(size_t)cur_n * 128 + f], accv);
    }
}

// ---------------- k_stats2: BN2 stats over g_nbr ------------------------------
__global__ __launch_bounds__(128) void k_stats2() {
    int f = threadIdx.x;
    int n0 = blockIdx.x * 200;     // grid 250
    float bs = 0.f, bq = 0.f;
    for (int n = n0; n < n0 + 200; n++) {
        float v = g_nbr[(size_t)n * 128 + f];
        bs += v; bq += v * v;
    }
    atomicAdd(&g_stats2[f],       bs);
    atomicAdd(&g_stats2[128 + f], bq);
}

// ---------------- k_fin2 ------------------------------------------------------
__global__ void k_fin2(const float* __restrict__ gamma2, const float* __restrict__ beta2) {
    int f = threadIdx.x;  // 128
    float inv = 1.f / (float)N_ATOM;
    float mean = g_stats2[f] * inv;
    float var  = g_stats2[128 + f] * inv - mean * mean;
    float sc = gamma2[f] * rsqrtf(var + EPS);
    g_bn2[f] = sc;
    g_bn2[128 + f] = beta2[f] - mean * sc;
}

// ---------------- k_out -------------------------------------------------------
__global__ void k_out(const float* __restrict__ atom, float* __restrict__ out) {
    int i = blockIdx.x * blockDim.x + threadIdx.x;
    if (i < N_ATOM * 128) {
        int f = i & 127;
        float v = atom[i] + g_nbr[i] * g_bn2[f] + g_bn2[128 + f];
        out[i] = softplusf(v);
    }
}

// ---------------- launch ------------------------------------------------------
extern "C" void kernel_launch(void* const* d_in, const int* in_sizes, int n_in,
                              void* d_out, int out_size) {
    const float* atom   = (const float*)d_in[0];
    const float* nbr    = (const float*)d_in[1];
    const int*   idxraw = (const int*)d_in[2];
    const float* W      = (const float*)d_in[3];
    const float* b      = (const float*)d_in[4];
    const float* gamma1 = (const float*)d_in[5];
    const float* beta1  = (const float*)d_in[6];
    const float* gamma2 = (const float*)d_in[7];
    const float* beta2  = (const float*)d_in[8];
    float* out = (float*)d_out;

    cudaFuncSetAttribute(k_pass1,   cudaFuncAttributeMaxDynamicSharedMemorySize, GB_TOTAL);
    cudaFuncSetAttribute(k_pass2,   cudaFuncAttributeMaxDynamicSharedMemorySize, P2_TOTAL);
    cudaFuncSetAttribute(k_sa_hmma, cudaFuncAttributeMaxDynamicSharedMemorySize, SB_TOTAL);

    k_detect<<<1, 256>>>(idxraw);
    k_convert<<<(NM_TOT + 255) / 256, 256>>>(idxraw);
    k_wconv<<<64, 256>>>(W);
    k_wconv2<<<256, 256>>>(W);
    k_sa_hmma<<<dim3(8, (N_ATOM + 127) / 128), 256, SB_TOTAL>>>(atom);
    k_pass1<<<dim3(2, (NM_TOT + 127) / 128), 256, GB_TOTAL>>>(nbr, b);
    k_fin1<<<1, 256>>>(gamma1, beta1);
    k_pass2<<<NM_TOT / 64, 256, P2_TOTAL>>>(nbr, b);
    k_stats2<<<250, 128>>>();
    k_fin2<<<1, 128>>>(gamma2, beta2);
    k_out<<<(N_ATOM * 128 + 255) / 256, 256>>>(atom, out);
}

// round 12
// speedup vs baseline: 1.8048x; 1.8048x over previous
#include <cuda_runtime.h>
#include <cuda_bf16.h>
#include <cstdint>

#define N_ATOM 50000
#define M_NBR  12
#define NM_TOT 600000
#define F_DIM  128
#define FAN_IN 320
#define EPS    1e-5f
#define CH     25

typedef unsigned long long ull;

#define PACK_F32X2(out, lo, hi) \
    asm("mov.b64 %0, {%1, %2};" : "=l"(out) : "f"(lo), "f"(hi))
#define UNPACK_F32X2(lo, hi, in) \
    asm("mov.b64 {%0, %1}, %2;" : "=f"(lo), "=f"(hi) : "l"(in))
#define FMA_F32X2(acc, a, b) \
    asm("fma.rn.f32x2 %0, %1, %2, %0;" : "+l"(acc) : "l"(a), "l"(b))

// ---------------- scratch ----------------------------------------------------
__device__ __align__(16) float g_SA[(size_t)N_ATOM * 512];      // [n][0:256)=S, [256:512)=A
__device__ __align__(16) float g_gated[(size_t)NM_TOT * 256];
__device__ __align__(16) float g_nbr[(size_t)N_ATOM * F_DIM];
__device__ float g_stats1[512];
__device__ float g_stats2[256];
__device__ float g_bn1[512];
__device__ float g_bn2[256];
__device__ int   g_idx32[NM_TOT];
__device__ __align__(16) __nv_bfloat16 g_WSh[512 * 128];   // [S|A] weights hi
__device__ __align__(16) __nv_bfloat16 g_WSl[512 * 128];   // [S|A] weights lo

__device__ __forceinline__ float softplusf(float x) {
    return fmaxf(x, 0.f) + __logf(1.f + __expf(-fabsf(x)));
}
__device__ __forceinline__ float sigmoidf(float x) {
    return 1.f / (1.f + __expf(-x));
}
__device__ __forceinline__ uint32_t smem_u32(const void* p) {
    uint32_t a;
    asm("{ .reg .u64 t; cvta.to.shared.u64 t, %1; cvt.u32.u64 %0, t; }"
        : "=r"(a) : "l"(p));
    return a;
}
__device__ __forceinline__ uint32_t pkbf(__nv_bfloat16 a, __nv_bfloat16 b) {
    __nv_bfloat162 t = __halves2bfloat162(a, b);
    return *(uint32_t*)&t;
}
__device__ __forceinline__ void ldsm_x4(uint32_t* r, uint32_t addr) {
    asm volatile("ldmatrix.sync.aligned.m8n8.x4.shared.b16 {%0,%1,%2,%3}, [%4];"
        : "=r"(r[0]), "=r"(r[1]), "=r"(r[2]), "=r"(r[3]) : "r"(addr));
}
__device__ __forceinline__ void mma_bf16(float* c, const uint32_t* a,
                                         uint32_t b0, uint32_t b1) {
    asm volatile("mma.sync.aligned.m16n8k16.row.col.f32.bf16.bf16.f32 "
        "{%0,%1,%2,%3}, {%4,%5,%6,%7}, {%8,%9}, {%0,%1,%2,%3};"
        : "+f"(c[0]), "+f"(c[1]), "+f"(c[2]), "+f"(c[3])
        : "r"(a[0]), "r"(a[1]), "r"(a[2]), "r"(a[3]), "r"(b0), "r"(b1));
}

// sa kernel smem layout (98304 B)
#define SB_A 0             // 128 rows x 32 chunks x 16B ([Xh|Xl], K=128)
#define SB_W 65536         // 64 rows x 32 chunks x 16B
#define SB_TOTAL 98304

// ---------------- k_convert: is64-detect + idx normalize + zero stats --------
__global__ void k_convert(const int* __restrict__ raw) {
    __shared__ int any;
    if (threadIdx.x == 0) any = 0;
    __syncthreads();
    if (threadIdx.x < 256 && raw[threadIdx.x * 2 + 1] != 0) atomicOr(&any, 1);
    __syncthreads();
    const int is64 = (any == 0);
    int i = blockIdx.x * blockDim.x + threadIdx.x;
    if (i < NM_TOT) g_idx32[i] = is64 ? raw[2 * i] : raw[i];
    if (i < 512) g_stats1[i] = 0.f;
    if (i < 256) g_stats2[i] = 0.f;
}

// ---------------- k_wsplit: both W splits in one kernel ----------------------
__global__ void k_wsplit(const float* __restrict__ W) {
    int i = blockIdx.x * blockDim.x + threadIdx.x;
    if (i < 512 * 128) {
        int f = i >> 7, k = i & 127;
        float w = (f < 256) ? W[f * FAN_IN + k] : W[(f - 256) * FAN_IN + 128 + k];
        __nv_bfloat16 h = __float2bfloat16(w);
        g_WSh[i] = h;
        g_WSl[i] = __float2bfloat16(w - __bfloat162float(h));
    }
}

// ---------------- k1: [S|A] via HMMA bf16 hi/lo (R9-proven) ------------------
__global__ __launch_bounds__(256) void k_sa_hmma(const float* __restrict__ atom) {
    extern __shared__ char smem[];
    const uint32_t sb = smem_u32(smem);
    const int tid = threadIdx.x;
    const int wid = tid >> 5, lane = tid & 31;
    const int fbase = blockIdx.x * 64;
    const int row0  = blockIdx.y * 128;
    const int rw0 = wid * 16;

    for (int t = tid; t < 2048; t += 256) {
        int r = t >> 4, c = t & 15;
        int gr = row0 + r; if (gr >= N_ATOM) gr = N_ATOM - 1;
        float4 v0 = *(const float4*)(atom + (size_t)gr * 128 + c * 8);
        float4 v1 = *(const float4*)(atom + (size_t)gr * 128 + c * 8 + 4);
        float xs[8] = {v0.x, v0.y, v0.z, v0.w, v1.x, v1.y, v1.z, v1.w};
        __nv_bfloat16 h[8]; float l[8];
#pragma unroll
        for (int q = 0; q < 8; q++) {
            h[q] = __float2bfloat16(xs[q]);
            l[q] = xs[q] - __bfloat162float(h[q]);
        }
        uint4 hh = make_uint4(pkbf(h[0], h[1]), pkbf(h[2], h[3]),
                              pkbf(h[4], h[5]), pkbf(h[6], h[7]));
        uint4 ll = make_uint4(
            pkbf(__float2bfloat16(l[0]), __float2bfloat16(l[1])),
            pkbf(__float2bfloat16(l[2]), __float2bfloat16(l[3])),
            pkbf(__float2bfloat16(l[4]), __float2bfloat16(l[5])),
            pkbf(__float2bfloat16(l[6]), __float2bfloat16(l[7])));
        int base = r * 512;
        *(uint4*)(smem + SB_A + base + (((c)      ^ (r & 7)) << 4)) = hh;
        *(uint4*)(smem + SB_A + base + (((c + 16) ^ (r & 7)) << 4)) = ll;
    }
    for (int t = tid; t < 1024; t += 256) {
        int r = t >> 4, c = t & 15;
        int gf = fbase + r;
        uint4 hh = *(const uint4*)((const char*)g_WSh + (size_t)gf * 256 + c * 16);
        uint4 ll = *(const uint4*)((const char*)g_WSl + (size_t)gf * 256 + c * 16);
        int base = r * 512;
        *(uint4*)(smem + SB_W + base + (((c)      ^ (r & 7)) << 4)) = hh;
        *(uint4*)(smem + SB_W + base + (((c + 16) ^ (r & 7)) << 4)) = ll;
    }
    __syncthreads();

    float acc[8][4];
#pragma unroll
    for (int i = 0; i < 8; i++)
#pragma unroll
        for (int j = 0; j < 4; j++) acc[i][j] = 0.f;

    const int arow = rw0 + (lane & 15);
    const uint32_t a_base = sb + SB_A + arow * 512;
    const int asel = lane >> 4;
    const int brow_l = ((lane >> 4) << 3) + (lane & 7);
    const int bsel = (lane >> 3) & 1;

#pragma unroll
    for (int s = 0; s < 24; s++) {
        int grp = s >> 3, ss = s & 7;          // 0:hh 1:hl 2:lh
        int ac = ((grp == 2) ? 16 : 0) + 2 * ss + asel;
        int bc = ((grp == 1) ? 16 : 0) + 2 * ss + bsel;
        uint32_t a[4];
        ldsm_x4(a, a_base + ((ac ^ (arow & 7)) << 4));
#pragma unroll
        for (int t = 0; t < 4; t++) {
            uint32_t b[4];
            int brow = t * 16 + brow_l;
            ldsm_x4(b, sb + SB_W + brow * 512 + ((bc ^ (brow & 7)) << 4));
            mma_bf16(acc[2 * t],     a, b[0], b[1]);
            mma_bf16(acc[2 * t + 1], a, b[2], b[3]);
        }
    }

    const int g = lane >> 2, tig = lane & 3;
#pragma unroll
    for (int nt = 0; nt < 8; nt++) {
        int col = fbase + nt * 8 + tig * 2;
#pragma unroll
        for (int rr = 0; rr < 2; rr++) {
            int gr = row0 + rw0 + g + rr * 8;
            if (gr < N_ATOM)
                *(float2*)(g_SA + (size_t)gr * 512 + col) =
                    make_float2(acc[nt][rr * 2], acc[nt][rr * 2 + 1]);
        }
    }
}

// ---------------- k2: E GEMM FFMA2 + fused gated + BN1 stats (R5-proven) -----
// BM=128 rows, BN=64 cols, grid (4, 4688), 256 threads, 3 CTAs/SM.
__global__ __launch_bounds__(256, 3) void k_gemm_gate(const float* __restrict__ nbr,
                                                      const float* __restrict__ W,
                                                      const float* __restrict__ bias) {
    __shared__ __align__(16) float Xs[32][128];   // [k][row]
    __shared__ __align__(16) float Ws[32][64];    // [k][f]
    __shared__ float s_stat[128];                 // sum[64], sumsq[64]
    const int tid = threadIdx.x;
    const int tx = tid & 15, ty = tid >> 4;
    const int fbase = blockIdx.x * 64;            // 0,64,128,192
    const int row0  = blockIdx.y * 128;

    ull acc[4][4];
#pragma unroll
    for (int p = 0; p < 4; p++)
#pragma unroll
        for (int c = 0; c < 4; c++) acc[p][c] = 0ULL;

    for (int kc = 0; kc < 64; kc += 32) {
        for (int t = tid; t < 1024; t += 256) {
            int r = t & 127, kq = t >> 7;          // kq 0..7
            int gr = row0 + r; if (gr >= NM_TOT) gr = NM_TOT - 1;
            float4 v = *(const float4*)(nbr + (size_t)gr * 64 + kc + kq * 4);
            Xs[kq * 4 + 0][r] = v.x; Xs[kq * 4 + 1][r] = v.y;
            Xs[kq * 4 + 2][r] = v.z; Xs[kq * 4 + 3][r] = v.w;
        }
        for (int t = tid; t < 512; t += 256) {
            int fl = t & 63, kq = t >> 6;          // kq 0..7
            float4 v = *(const float4*)(W + (size_t)(fbase + fl) * FAN_IN + 256 + kc + kq * 4);
            Ws[kq * 4 + 0][fl] = v.x; Ws[kq * 4 + 1][fl] = v.y;
            Ws[kq * 4 + 2][fl] = v.z; Ws[kq * 4 + 3][fl] = v.w;
        }
        __syncthreads();
#pragma unroll 8
        for (int k = 0; k < 32; k++) {
            ulonglong2 A01 = *(ulonglong2*)&Xs[k][ty * 8];
            ulonglong2 A23 = *(ulonglong2*)&Xs[k][ty * 8 + 4];
            float4 Bv = *(float4*)&Ws[k][tx * 4];
            ull b0, b1, b2, b3;
            PACK_F32X2(b0, Bv.x, Bv.x); PACK_F32X2(b1, Bv.y, Bv.y);
            PACK_F32X2(b2, Bv.z, Bv.z); PACK_F32X2(b3, Bv.w, Bv.w);
            FMA_F32X2(acc[0][0], A01.x, b0); FMA_F32X2(acc[0][1], A01.x, b1);
            FMA_F32X2(acc[0][2], A01.x, b2); FMA_F32X2(acc[0][3], A01.x, b3);
            FMA_F32X2(acc[1][0], A01.y, b0); FMA_F32X2(acc[1][1], A01.y, b1);
            FMA_F32X2(acc[1][2], A01.y, b2); FMA_F32X2(acc[1][3], A01.y, b3);
            FMA_F32X2(acc[2][0], A23.x, b0); FMA_F32X2(acc[2][1], A23.x, b1);
            FMA_F32X2(acc[2][2], A23.x, b2); FMA_F32X2(acc[2][3], A23.x, b3);
            FMA_F32X2(acc[3][0], A23.y, b0); FMA_F32X2(acc[3][1], A23.y, b1);
            FMA_F32X2(acc[3][2], A23.y, b2); FMA_F32X2(acc[3][3], A23.y, b3);
        }
        __syncthreads();
    }

    if (tid < 128) s_stat[tid] = 0.f;
    __syncthreads();

    const float4 bia = *(const float4*)(bias + fbase + tx * 4);
    float sums[4] = {0.f, 0.f, 0.f, 0.f}, sqs[4] = {0.f, 0.f, 0.f, 0.f};

#pragma unroll
    for (int p = 0; p < 4; p++) {
        float l0, h0, l1, h1, l2, h2, l3, h3;
        UNPACK_F32X2(l0, h0, acc[p][0]);
        UNPACK_F32X2(l1, h1, acc[p][1]);
        UNPACK_F32X2(l2, h2, acc[p][2]);
        UNPACK_F32X2(l3, h3, acc[p][3]);
#pragma unroll
        for (int s = 0; s < 2; s++) {
            float e0 = s ? h0 : l0, e1 = s ? h1 : l1;
            float e2 = s ? h2 : l2, e3 = s ? h3 : l3;
            int nm = row0 + ty * 8 + 2 * p + s;
            if (nm >= NM_TOT) continue;
            int n = nm / 12;
            int j = g_idx32[nm];
            float msk = (j != 0) ? 1.f : 0.f;
            int col = fbase + tx * 4;
            float4 s4 = *(const float4*)(g_SA + (size_t)n * 512 + col);
            float4 a4 = *(const float4*)(g_SA + (size_t)j * 512 + 256 + col);
            float g0 = s4.x + bia.x + msk * (a4.x + e0);
            float g1 = s4.y + bia.y + msk * (a4.y + e1);
            float g2 = s4.z + bia.z + msk * (a4.z + e2);
            float g3 = s4.w + bia.w + msk * (a4.w + e3);
            *(float4*)(g_gated + (size_t)nm * 256 + col) = make_float4(g0, g1, g2, g3);
            sums[0] += g0; sqs[0] += g0 * g0;
            sums[1] += g1; sqs[1] += g1 * g1;
            sums[2] += g2; sqs[2] += g2 * g2;
            sums[3] += g3; sqs[3] += g3 * g3;
        }
    }
#pragma unroll
    for (int c = 0; c < 4; c++) {
        int lc = tx * 4 + c;
        atomicAdd(&s_stat[lc], sums[c]);
        atomicAdd(&s_stat[64 + lc], sqs[c]);
    }
    __syncthreads();
    if (tid < 64) {
        atomicAdd(&g_stats1[fbase + tid],       s_stat[tid]);
        atomicAdd(&g_stats1[256 + fbase + tid], s_stat[64 + tid]);
    }
}

// ---------------- k3: finalize BN1 affine ------------------------------------
__global__ void k_fin1(const float* __restrict__ gamma1, const float* __restrict__ beta1) {
    int f = threadIdx.x;  // 256
    float inv = 1.f / (float)NM_TOT;
    float mean = g_stats1[f] * inv;
    float var  = g_stats1[256 + f] * inv - mean * mean;
    float sc = gamma1[f] * rsqrtf(var + EPS);
    g_bn1[f] = sc;
    g_bn1[256 + f] = beta1[f] - mean * sc;
}

// ---------------- k4: gate + sum over M + BN2 stats --------------------------
__global__ __launch_bounds__(128) void k_reduce() {
    const int f = threadIdx.x;
    const int n0 = blockIdx.x * CH;
    const float sc_f = g_bn1[f],        sh_f = g_bn1[256 + f];
    const float sc_c = g_bn1[128 + f],  sh_c = g_bn1[256 + 128 + f];
    float bs = 0.f, bq = 0.f;
    for (int n = n0; n < n0 + CH; n++) {
        float acc = 0.f;
#pragma unroll
        for (int m = 0; m < 12; m++) {
            int nm = n * 12 + m;
            int j = g_idx32[nm];
            if (j != 0) {
                float gf = g_gated[(size_t)nm * 256 + f]       * sc_f + sh_f;
                float gc = g_gated[(size_t)nm * 256 + 128 + f] * sc_c + sh_c;
                acc += sigmoidf(gf) * softplusf(gc);
            }
        }
        g_nbr[(size_t)n * 128 + f] = acc;
        bs += acc; bq += acc * acc;
    }
    atomicAdd(&g_stats2[f],       bs);
    atomicAdd(&g_stats2[128 + f], bq);
}

// ---------------- k5: finalize BN2 affine ------------------------------------
__global__ void k_fin2(const float* __restrict__ gamma2, const float* __restrict__ beta2) {
    int f = threadIdx.x;  // 128
    float inv = 1.f / (float)N_ATOM;
    float mean = g_stats2[f] * inv;
    float var  = g_stats2[128 + f] * inv - mean * mean;
    float sc = gamma2[f] * rsqrtf(var + EPS);
    g_bn2[f] = sc;
    g_bn2[128 + f] = beta2[f] - mean * sc;
}

// ---------------- k6: out = softplus(atom + BN2(nbr_sumed)) ------------------
__global__ void k_out(const float* __restrict__ atom, float* __restrict__ out) {
    int i = blockIdx.x * blockDim.x + threadIdx.x;
    if (i < N_ATOM * 128) {
        int f = i & 127;
        float v = atom[i] + g_nbr[i] * g_bn2[f] + g_bn2[128 + f];
        out[i] = softplusf(v);
    }
}

// ---------------- launch ------------------------------------------------------
extern "C" void kernel_launch(void* const* d_in, const int* in_sizes, int n_in,
                              void* d_out, int out_size) {
    const float* atom   = (const float*)d_in[0];
    const float* nbr    = (const float*)d_in[1];
    const int*   idxraw = (const int*)d_in[2];
    const float* W      = (const float*)d_in[3];
    const float* b      = (const float*)d_in[4];
    const float* gamma1 = (const float*)d_in[5];
    const float* beta1  = (const float*)d_in[6];
    const float* gamma2 = (const float*)d_in[7];
    const float* beta2  = (const float*)d_in[8];
    float* out = (float*)d_out;

    cudaFuncSetAttribute(k_sa_hmma, cudaFuncAttributeMaxDynamicSharedMemorySize, SB_TOTAL);

    k_convert<<<(NM_TOT + 255) / 256, 256>>>(idxraw);                 // 1
    k_wsplit<<<(512 * 128 + 255) / 256, 256>>>(W);                    // 2
    k_sa_hmma<<<dim3(8, (N_ATOM + 127) / 128), 256, SB_TOTAL>>>(atom);// 3
    k_gemm_gate<<<dim3(4, (NM_TOT + 127) / 128), 256>>>(nbr, W, b);   // 4 <- profiled
    k_fin1<<<1, 256>>>(gamma1, beta1);
    k_reduce<<<N_ATOM / CH, 128>>>();
    k_fin2<<<1, 128>>>(gamma2, beta2);
    k_out<<<(N_ATOM * 128 + 255) / 256, 256>>>(atom, out);
}